// round 12
// baseline (speedup 1.0000x reference)
#include <cuda_runtime.h>
#include <cuda_fp16.h>
#include <cstdint>

#define P       4096
#define MOUT    64
#define ITILE   128
#define TILES   (P / ITILE)      // 32
#define SPLITS  8
#define KSPLIT  (P / SPLITS)     // 512
#define KC      32               // k per chunk (raw int32 A: 128 rows x 128 B)
#define NCHUNK  (KSPLIT / KC)    // 16
#define NBUF    3
#define NT      256
#define EXP_NEG 0.36787907f      // expf(-1.000001f)

// ---------------- device scratch ----------------
__device__ float g_Dpart[SPLITS][P][MOUT];   // split partials (8 MB)
__device__ int   g_cnt[SPLITS][P];
__device__ int   g_total;                    // sticky any-neighbor flag (replay-safe)
__device__ int   g_tilectr[TILES];           // self-resetting completion counters

// ---------------- helpers ----------------
__device__ __forceinline__ uint32_t smem_u32(const void* p) {
    uint32_t a;
    asm("{ .reg .u64 t; cvta.to.shared.u64 t, %1; cvt.u32.u64 %0, t; }" : "=r"(a) : "l"(p));
    return a;
}
// 128-B rows, 8x16B chunks: chunk' = chunk ^ (row&7)
__device__ __forceinline__ uint32_t swz(int row, int kbyte) {
    return (uint32_t)(row * 128) + (uint32_t)((((kbyte >> 4) ^ (row & 7)) << 4) | (kbyte & 15));
}
__device__ __forceinline__ void sts64(uint32_t addr, uint32_t x, uint32_t y) {
    asm volatile("st.shared.v2.b32 [%0], {%1, %2};" :: "r"(addr), "r"(x), "r"(y) : "memory");
}
__device__ __forceinline__ void lds128(uint32_t* v, uint32_t addr) {
    asm volatile("ld.shared.v4.b32 {%0,%1,%2,%3}, [%4];"
                 : "=r"(v[0]), "=r"(v[1]), "=r"(v[2]), "=r"(v[3]) : "r"(addr));
}
__device__ __forceinline__ void cp16(uint32_t dst, const void* src) {
    asm volatile("cp.async.cg.shared.global [%0], [%1], 16;" :: "r"(dst), "l"(src) : "memory");
}
#define CP_COMMIT() asm volatile("cp.async.commit_group;" ::: "memory")
#define CP_WAIT1()  asm volatile("cp.async.wait_group 1;" ::: "memory")
__device__ __forceinline__ void ldsm4t(uint32_t* r, uint32_t addr) {
    asm volatile("ldmatrix.sync.aligned.m8n8.x4.trans.shared.b16 {%0,%1,%2,%3}, [%4];"
                 : "=r"(r[0]), "=r"(r[1]), "=r"(r[2]), "=r"(r[3]) : "r"(addr));
}
__device__ __forceinline__ void mma16816(float* c, const uint32_t* a, const uint32_t* b) {
    asm volatile("mma.sync.aligned.m16n8k16.row.col.f32.f16.f16.f32 "
                 "{%0,%1,%2,%3}, {%4,%5,%6,%7}, {%8,%9}, {%0,%1,%2,%3};"
                 : "+f"(c[0]), "+f"(c[1]), "+f"(c[2]), "+f"(c[3])
                 : "r"(a[0]), "r"(a[1]), "r"(a[2]), "r"(a[3]), "r"(b[0]), "r"(b[1]));
}

// ---------------- single fused kernel ----------------
// smem: [A0 16K][A1 16K][A2 16K][B 64K] = 112 KB
extern __shared__ __align__(16) char smem[];

__global__ __launch_bounds__(NT, 2)
void social_fused(const float* __restrict__ hidden,
                  const int*   __restrict__ nei,
                  float*       __restrict__ out) {
    const int tid    = threadIdx.x;
    const int lane   = tid & 31;
    const int w      = tid >> 5;
    const int warp_m = w & 3;            // i-rows warp_m*32 .. +31
    const int warp_n = w >> 2;           // n-cols warp_n*32 .. +31
    const int split  = blockIdx.x;
    const int tile   = blockIdx.y;
    const int i0     = tile * ITILE;
    const int k0base = split * KSPLIT;

    const uint32_t sbase = smem_u32(smem);
    const uint32_t sA[NBUF] = {sbase, sbase + 16384, sbase + 32768};
    const uint32_t sBP      = sbase + 49152;   // persistent B: 512 logical-k rows x 128 B

    float acc[2][4][4];
    #pragma unroll
    for (int a = 0; a < 2; ++a)
        #pragma unroll
        for (int b = 0; b < 4; ++b)
            #pragma unroll
            for (int c = 0; c < 4; ++c) acc[a][b][c] = 0.0f;
    int cnt[2][2] = {{0, 0}, {0, 0}};          // [mt][half] row counts (warp_n==0 only)

    auto issue_A = [&](int c) {                // raw int32 mask tile, 16 KB via cp.async
        const int k0 = k0base + c * KC;
        const uint32_t dstb = sA[c % NBUF];
        #pragma unroll
        for (int q = 0; q < 4; ++q) {
            int idx = q * NT + tid;
            int r = idx >> 3, ch = idx & 7;    // 128 rows x 8 chunks of 16B
            cp16(dstb + (uint32_t)(r * 128) + (uint32_t)(((ch ^ (r & 7)) << 4)),
                 nei + (size_t)(i0 + r) * P + k0 + ch * 4);
        }
    };

    // ---- start the async pipeline immediately
    issue_A(0); CP_COMMIT();
    issue_A(1); CP_COMMIT();

    // ---- one-time B init: hidden fp32 [k][m] -> fp16 smem at PERMUTED logical k rows.
    // Logical k within each 16-group: physical p=(4t+j) -> logical 2t+(j&1)+8*(j>>1),
    // matching the a-fragment built from contiguous physical ints below.
    #pragma unroll
    for (int q = 0; q < 32; ++q) {
        int idx = q * NT + tid;                // 512 k-rows x 16 m-quads
        int kg = idx >> 4, mq4 = (idx & 15) * 4;
        int p16 = kg & 15, t = p16 >> 2, j = p16 & 3;
        int Lg = (kg & ~15) | (2 * t + (j & 1) + 8 * (j >> 1));
        float4 v = *reinterpret_cast<const float4*>(
            hidden + (size_t)(k0base + kg) * MOUT + mq4);        // L2-resident (1 MB)
        __half2 h01 = __floats2half2_rn(v.x, v.y);
        __half2 h23 = __floats2half2_rn(v.z, v.w);
        sts64(sBP + swz(Lg, mq4 * 2),
              *reinterpret_cast<uint32_t*>(&h01), *reinterpret_cast<uint32_t*>(&h23));
    }

    #pragma unroll 1
    for (int c = 0; c < NCHUNK; ++c) {
        CP_WAIT1();                 // chunk c landed (latest pending is c+1 / empty)
        __syncthreads();            // block-wide visibility (also covers B init once)
        if (c + 2 < NCHUNK) issue_A(c + 2);
        CP_COMMIT();                // empty group in tail iters keeps wait semantics

        const uint32_t sAb = sA[c % NBUF];
        #pragma unroll
        for (int k16 = 0; k16 < KC / 16; ++k16) {
            uint32_t bfr[2][4];
            #pragma unroll
            for (int g = 0; g < 2; ++g) {      // B: trans-load, logical k rows
                int krow = c * KC + k16 * 16 + (lane & 15);
                int mb   = warp_n * 32 + g * 16 + ((lane >> 4) << 3);
                ldsm4t(bfr[g], sBP + swz(krow, mb * 2));
            }
            #pragma unroll
            for (int mt = 0; mt < 2; ++mt) {
                // A fragment straight from raw ints: one LDS.128 per row of the pair
                int r  = warp_m * 32 + mt * 16 + (lane >> 2);
                int kb = k16 * 64 + (lane & 3) * 16;
                uint32_t q0[4], q1[4], afr[4];
                lds128(q0, sAb + swz(r,     kb));
                lds128(q1, sAb + swz(r + 8, kb));
                afr[0] = q0[0] * 0x3C00u + q0[1] * 0x3C000000u;  // v in {0,1} -> fp16 {0,1}
                afr[1] = q1[0] * 0x3C00u + q1[1] * 0x3C000000u;
                afr[2] = q0[2] * 0x3C00u + q0[3] * 0x3C000000u;
                afr[3] = q1[2] * 0x3C00u + q1[3] * 0x3C000000u;
                if (warp_n == 0) {             // avoid double count (warp_n=1 reads same A)
                    cnt[mt][0] += q0[0] + q0[1] + q0[2] + q0[3];
                    cnt[mt][1] += q1[0] + q1[1] + q1[2] + q1[3];
                }
                #pragma unroll
                for (int g = 0; g < 2; ++g) {
                    mma16816(acc[mt][2 * g],     afr, &bfr[g][0]);  // n +0..7
                    mma16816(acc[mt][2 * g + 1], afr, &bfr[g][2]);  // n +8..15
                }
            }
        }
    }

    // ---- counts: 4 lanes per row (lane&3 = k-slices) -> quad shfl reduce
    if (warp_n == 0) {
        int any = 0;
        #pragma unroll
        for (int mt = 0; mt < 2; ++mt)
            #pragma unroll
            for (int h = 0; h < 2; ++h) {
                int v = cnt[mt][h];
                v += __shfl_xor_sync(0xffffffffu, v, 1);
                v += __shfl_xor_sync(0xffffffffu, v, 2);
                if ((lane & 3) == 0) {
                    g_cnt[split][i0 + warp_m * 32 + mt * 16 + (lane >> 2) + h * 8] = v;
                    any |= v;
                }
            }
        if ((lane & 3) == 0 && any) atomicOr(&g_total, 1);   // idempotent, replay-safe
    }

    // ---- write split partials (mapping identical to validated R9-R11 epilogue)
    #pragma unroll
    for (int mt = 0; mt < 2; ++mt) {
        int ibase = i0 + warp_m * 32 + mt * 16 + (lane >> 2);
        #pragma unroll
        for (int g = 0; g < 2; ++g)
            #pragma unroll
            for (int t = 0; t < 2; ++t) {
                int n0 = warp_n * 32 + g * 16 + t * 8 + 2 * (lane & 3);
                const float* cfr = acc[mt][2 * g + t];
                *reinterpret_cast<float2*>(&g_Dpart[split][ibase][n0]) =
                    make_float2(cfr[0], cfr[1]);
                *reinterpret_cast<float2*>(&g_Dpart[split][ibase + 8][n0]) =
                    make_float2(cfr[2], cfr[3]);
            }
    }

    // ---- completion protocol (threadfence-reduction pattern)
    __threadfence();
    __syncthreads();
    __shared__ int s_last;
    if (tid == 0) s_last = atomicAdd(&g_tilectr[tile], 1);
    __syncthreads();
    if (s_last != SPLITS - 1) return;

    // ---- last CTA of this i-tile: combine splits + analytic softmax scale
    __threadfence();
    const int gt = g_total;
    #pragma unroll
    for (int rr = 0; rr < 4; ++rr) {
        int loc = (rr * NT + tid) * 8;          // 0..8191 within tile
        int i   = i0 + (loc >> 6);
        int col = loc & 63;
        if (gt > 0) {
            float4 s0 = make_float4(0.f, 0.f, 0.f, 0.f), s1 = s0;
            #pragma unroll
            for (int sp = 0; sp < SPLITS; ++sp) {
                float4 a4 = *reinterpret_cast<const float4*>(&g_Dpart[sp][i][col]);
                float4 b4 = *reinterpret_cast<const float4*>(&g_Dpart[sp][i][col + 4]);
                s0.x += a4.x; s0.y += a4.y; s0.z += a4.z; s0.w += a4.w;
                s1.x += b4.x; s1.y += b4.y; s1.z += b4.z; s1.w += b4.w;
            }
            int csum = 0;
            #pragma unroll
            for (int sp = 0; sp < SPLITS; ++sp) csum += g_cnt[sp][i];
            float cn = (float)csum;
            float inv = 1.0f / (cn + ((float)P - cn) * EXP_NEG);
            s0.x *= inv; s0.y *= inv; s0.z *= inv; s0.w *= inv;
            s1.x *= inv; s1.y *= inv; s1.z *= inv; s1.w *= inv;
            *reinterpret_cast<float4*>(out + (size_t)i * MOUT + col)     = s0;
            *reinterpret_cast<float4*>(out + (size_t)i * MOUT + col + 4) = s1;
        } else {
            *reinterpret_cast<float4*>(out + (size_t)i * MOUT + col) =
                *reinterpret_cast<const float4*>(hidden + (size_t)i * MOUT + col);
            *reinterpret_cast<float4*>(out + (size_t)i * MOUT + col + 4) =
                *reinterpret_cast<const float4*>(hidden + (size_t)i * MOUT + col + 4);
        }
    }
    if (tid == 0) g_tilectr[tile] = 0;          // self-reset -> next graph replay sees 0
}

// ---------------- launch: ONE kernel ----------------
extern "C" void kernel_launch(void* const* d_in, const int* in_sizes, int n_in,
                              void* d_out, int out_size) {
    const float* hidden = (const float*)d_in[0];
    // d_in[1] (corr_index) is unused by the reference math — never read.
    const int*   nei    = (const int*)d_in[2];
    float*       out    = (float*)d_out;

    const int smem_bytes = 114688;   // 3x16K A + 64K persistent B
    cudaFuncSetAttribute(social_fused,
                         cudaFuncAttributeMaxDynamicSharedMemorySize, smem_bytes);

    social_fused<<<dim3(SPLITS, TILES), NT, smem_bytes>>>(hidden, nei, out);
}